// round 4
// baseline (speedup 1.0000x reference)
#include <cuda_runtime.h>
#include <cuda_fp16.h>
#include <mma.h>
#include <math.h>

using namespace nvcuda;

#define N_NODES   40000
#define N_EDGES   640000
#define FDIM      128
#define N_GRAPHS  64
#define N_CLASSES 10

#define SCAN_B    1024
#define SCAN_NB   ((N_NODES + SCAN_B - 1) / SCAN_B)   // 40

// ---------------- scratch (device globals; no allocations) ------------------
__device__ __align__(16) __half g_X16[N_NODES * FDIM];  // fp16 input features
__device__ __align__(16) __half g_A16[N_NODES * FDIM];  // layer outputs, fp16
__device__ __align__(16) __half g_B16[N_NODES * FDIM];  // gemm output, fp16
__device__ __align__(16) __half g_W16[3 * FDIM * FDIM]; // weights fp16
__device__ int    g_indeg[N_NODES];
__device__ float  g_dis[N_NODES];
__device__ int    g_off[N_NODES];
__device__ int    g_cursor[N_NODES];
__device__ int    g_bsum[SCAN_NB];
__device__ int2   g_srcwt[N_EDGES];        // CSR payload: (src row, norm bits)
__device__ float  g_sums[N_GRAPHS * FDIM];
__device__ float  g_cnts[N_GRAPHS];

// ---------------- conversions ------------------------------------------------
__global__ void x_to_h_kernel(const float* __restrict__ x) {
    int idx = blockIdx.x * blockDim.x + threadIdx.x;   // float4 units
    if (idx >= N_NODES * 32) return;
    float4 v = ((const float4*)x)[idx];
    __half2 h0 = __floats2half2_rn(v.x, v.y);
    __half2 h1 = __floats2half2_rn(v.z, v.w);
    uint2 u; u.x = *(unsigned*)&h0; u.y = *(unsigned*)&h1;
    ((uint2*)g_X16)[idx] = u;
}

__global__ void w_to_h_kernel(const float* __restrict__ W1,
                              const float* __restrict__ W2,
                              const float* __restrict__ W3) {
    int idx = blockIdx.x * blockDim.x + threadIdx.x;   // per element
    if (idx >= FDIM * FDIM) return;
    g_W16[idx]                 = __float2half_rn(W1[idx]);
    g_W16[idx + FDIM * FDIM]   = __float2half_rn(W2[idx]);
    g_W16[idx + 2 * FDIM*FDIM] = __float2half_rn(W3[idx]);
}

// ---------------- degree ----------------------------------------------------
__global__ void deg_init_kernel() {
    int i = blockIdx.x * blockDim.x + threadIdx.x;
    if (i < N_NODES) g_indeg[i] = 0;
}

__global__ void deg_count_kernel(const int* __restrict__ col) {
    int e = blockIdx.x * blockDim.x + threadIdx.x;
    if (e < N_EDGES) atomicAdd(&g_indeg[col[e]], 1);
}

__global__ void dis_kernel() {
    int i = blockIdx.x * blockDim.x + threadIdx.x;
    if (i < N_NODES) g_dis[i] = rsqrtf((float)(g_indeg[i] + 1));
}

// ---------------- exclusive scan of g_indeg -> g_off ------------------------
__global__ void scanA_kernel() {
    __shared__ int s[SCAN_B];
    int tid = threadIdx.x;
    int gid = blockIdx.x * SCAN_B + tid;
    int v = (gid < N_NODES) ? g_indeg[gid] : 0;
    s[tid] = v;
    __syncthreads();
#pragma unroll
    for (int off = 1; off < SCAN_B; off <<= 1) {
        int t = 0;
        if (tid >= off) t = s[tid - off];
        __syncthreads();
        if (tid >= off) s[tid] += t;
        __syncthreads();
    }
    if (gid < N_NODES) g_off[gid] = s[tid] - v;
    if (tid == SCAN_B - 1) g_bsum[blockIdx.x] = s[tid];
}

__global__ void scanB_kernel() {
    if (threadIdx.x == 0) {
        int run = 0;
        for (int i = 0; i < SCAN_NB; i++) {
            int t = g_bsum[i];
            g_bsum[i] = run;
            run += t;
        }
    }
}

__global__ void scanC_kernel() {
    int gid = blockIdx.x * SCAN_B + threadIdx.x;
    if (gid < N_NODES) {
        int o = g_off[gid] + g_bsum[blockIdx.x];
        g_off[gid] = o;
        g_cursor[gid] = o;
    }
}

// ---------------- CSR fill ---------------------------------------------------
__global__ void fill_kernel(const int* __restrict__ row,
                            const int* __restrict__ col) {
    int e = blockIdx.x * blockDim.x + threadIdx.x;
    if (e >= N_EDGES) return;
    int r = row[e];
    int c = col[e];
    int p = atomicAdd(&g_cursor[c], 1);
    float w = g_dis[r] * g_dis[c];
    g_srcwt[p] = make_int2(r, __float_as_int(w));
}

// ---------------- wmma GEMM: Y16[64rows,128] = X16 @ W16 --------------------
// Block 256 thr (8 warps). Warp (wr,wc): rows wr*16..+16, cols wc*64..+64.
#define GEMM_BM 64
#define GEMM_SMEM_BYTES ((128*128 + GEMM_BM*128) * 2 + GEMM_BM * 128 * 4)
__global__ void gemm_wmma_kernel(const __half* __restrict__ X,
                                 const __half* __restrict__ W,
                                 __half* __restrict__ Y) {
    extern __shared__ __half smh[];
    __half* Ws = smh;                         // 128x128 half (32 KB)
    __half* Xs = smh + 128 * 128;             // 64x128 half  (16 KB)
    float*  Os = (float*)(smh + 128*128 + GEMM_BM*128);  // 64x128 f32 (32 KB)

    int tid  = threadIdx.x;
    int row0 = blockIdx.x * GEMM_BM;

    // load W: 2048 float4
    const float4* W4 = (const float4*)W;
    float4* Ws4 = (float4*)Ws;
#pragma unroll
    for (int i = 0; i < 8; i++) Ws4[tid + 256 * i] = W4[tid + 256 * i];

    // load X tile: 1024 float4
    const float4* X4 = (const float4*)(X + (size_t)row0 * FDIM);
    float4* Xs4 = (float4*)Xs;
#pragma unroll
    for (int i = 0; i < 4; i++) Xs4[tid + 256 * i] = X4[tid + 256 * i];
    __syncthreads();

    int warp = tid >> 5;
    int wr = warp >> 1;        // 0..3  row tile
    int wc = warp & 1;         // 0..1  col half

    wmma::fragment<wmma::matrix_a, 16, 16, 16, __half, wmma::row_major> a_frag;
    wmma::fragment<wmma::matrix_b, 16, 16, 16, __half, wmma::row_major> b_frag;
    wmma::fragment<wmma::accumulator, 16, 16, 16, float> acc[4];
#pragma unroll
    for (int j = 0; j < 4; j++) wmma::fill_fragment(acc[j], 0.0f);

#pragma unroll
    for (int kk = 0; kk < 8; kk++) {
        wmma::load_matrix_sync(a_frag, Xs + (wr * 16) * 128 + kk * 16, 128);
#pragma unroll
        for (int j = 0; j < 4; j++) {
            wmma::load_matrix_sync(b_frag, Ws + (kk * 16) * 128 + wc * 64 + j * 16, 128);
            wmma::mma_sync(acc[j], a_frag, b_frag, acc[j]);
        }
    }

#pragma unroll
    for (int j = 0; j < 4; j++)
        wmma::store_matrix_sync(Os + (wr * 16) * 128 + wc * 64 + j * 16, acc[j],
                                128, wmma::mem_row_major);
    __syncthreads();

    // convert + write: 2048 uint2 (each = 4 half)
    const float4* Os4 = (const float4*)Os;
#pragma unroll
    for (int i = 0; i < 8; i++) {
        int idx = tid + 256 * i;
        float4 v = Os4[idx];
        __half2 h0 = __floats2half2_rn(v.x, v.y);
        __half2 h1 = __floats2half2_rn(v.z, v.w);
        uint2 u; u.x = *(unsigned*)&h0; u.y = *(unsigned*)&h1;
        int r = idx >> 5, c = idx & 31;
        ((uint2*)(Y + (size_t)(row0 + r) * FDIM))[c] = u;
    }
}

// ---------------- fp16 quad -> float4 ---------------------------------------
__device__ __forceinline__ float4 h4_to_f4(uint2 u) {
    __half2 a = *(__half2*)&u.x;
    __half2 b = *(__half2*)&u.y;
    float2 fa = __half22float2(a);
    float2 fb = __half22float2(b);
    return make_float4(fa.x, fa.y, fb.x, fb.y);
}

// ---------------- CSR gather: A16[n] = relu( sum_in + selfloop + bias ) -----
__global__ void gather_kernel(const float* __restrict__ bias) {
    int node = blockIdx.x * (blockDim.x >> 5) + (threadIdx.x >> 5);
    if (node >= N_NODES) return;
    int lane = threadIdx.x & 31;

    const uint2* B2 = (const uint2*)g_B16;

    int beg = g_off[node];
    int end = beg + g_indeg[node];

    float dn = g_dis[node];
    float sl = dn * dn;
    float4 sv = h4_to_f4(B2[(size_t)node * 32 + lane]);
    float4 acc = make_float4(sv.x * sl, sv.y * sl, sv.z * sl, sv.w * sl);

    int i = beg;
    for (; i + 2 <= end; i += 2) {
        int2 e0 = g_srcwt[i];
        int2 e1 = g_srcwt[i + 1];
        float w0 = __int_as_float(e0.y);
        float w1 = __int_as_float(e1.y);
        float4 v0 = h4_to_f4(B2[(size_t)e0.x * 32 + lane]);
        float4 v1 = h4_to_f4(B2[(size_t)e1.x * 32 + lane]);
        acc.x = fmaf(w0, v0.x, acc.x);  acc.y = fmaf(w0, v0.y, acc.y);
        acc.z = fmaf(w0, v0.z, acc.z);  acc.w = fmaf(w0, v0.w, acc.w);
        acc.x = fmaf(w1, v1.x, acc.x);  acc.y = fmaf(w1, v1.y, acc.y);
        acc.z = fmaf(w1, v1.z, acc.z);  acc.w = fmaf(w1, v1.w, acc.w);
    }
    if (i < end) {
        int2 e0 = g_srcwt[i];
        float w0 = __int_as_float(e0.y);
        float4 v0 = h4_to_f4(B2[(size_t)e0.x * 32 + lane]);
        acc.x = fmaf(w0, v0.x, acc.x);  acc.y = fmaf(w0, v0.y, acc.y);
        acc.z = fmaf(w0, v0.z, acc.z);  acc.w = fmaf(w0, v0.w, acc.w);
    }

    float4 bv = __ldg(&((const float4*)bias)[lane]);
    acc.x = fmaxf(acc.x + bv.x, 0.f);
    acc.y = fmaxf(acc.y + bv.y, 0.f);
    acc.z = fmaxf(acc.z + bv.z, 0.f);
    acc.w = fmaxf(acc.w + bv.w, 0.f);

    __half2 h0 = __floats2half2_rn(acc.x, acc.y);
    __half2 h1 = __floats2half2_rn(acc.z, acc.w);
    uint2 u; u.x = *(unsigned*)&h0; u.y = *(unsigned*)&h1;
    ((uint2*)g_A16)[(size_t)node * 32 + lane] = u;
}

// ---------------- pooling ----------------------------------------------------
__global__ void zero_pool_kernel() {
    int i = threadIdx.x;
    for (int k = i; k < N_GRAPHS * FDIM; k += blockDim.x) g_sums[k] = 0.f;
    if (i < N_GRAPHS) g_cnts[i] = 0.f;
}

__global__ void pool_kernel(const int* __restrict__ batch) {
    int node = blockIdx.x * (blockDim.x >> 5) + (threadIdx.x >> 5);
    if (node >= N_NODES) return;
    int lane = threadIdx.x & 31;
    int g = __ldg(&batch[node]);
    float4 v = h4_to_f4(((const uint2*)g_A16)[(size_t)node * 32 + lane]);
    float* dst = g_sums + (size_t)g * FDIM + lane * 4;
    asm volatile("red.global.add.v4.f32 [%0], {%1, %2, %3, %4};"
                 :: "l"(dst), "f"(v.x), "f"(v.y), "f"(v.z), "f"(v.w)
                 : "memory");
    if (lane == 0) atomicAdd(&g_cnts[g], 1.0f);
}

// ---------------- final linear ----------------------------------------------
__global__ void final_kernel(const float* __restrict__ Wl,
                             const float* __restrict__ bl,
                             float* __restrict__ out) {
    int g = blockIdx.x;
    int c = threadIdx.x;
    if (c >= N_CLASSES) return;
    float cnt = g_cnts[g];
    float inv = 1.0f / fmaxf(cnt, 1.0f);
    float acc = bl[c];
    for (int k = 0; k < FDIM; k++)
        acc += (g_sums[g * FDIM + k] * inv) * Wl[k * N_CLASSES + c];
    out[g * N_CLASSES + c] = acc;
}

// ---------------- launch ----------------------------------------------------
extern "C" void kernel_launch(void* const* d_in, const int* in_sizes, int n_in,
                              void* d_out, int out_size) {
    const float* x   = (const float*)d_in[0];
    const int*   ei  = (const int*)d_in[1];
    const int*   bat = (const int*)d_in[2];
    const float* W1  = (const float*)d_in[3];
    const float* b1  = (const float*)d_in[4];
    const float* W2  = (const float*)d_in[5];
    const float* b2  = (const float*)d_in[6];
    const float* W3  = (const float*)d_in[7];
    const float* b3  = (const float*)d_in[8];
    const float* Wl  = (const float*)d_in[9];
    const float* bl  = (const float*)d_in[10];
    float* out = (float*)d_out;

    const int* row = ei;
    const int* col = ei + N_EDGES;

    static bool attr_set = false;
    if (!attr_set) {
        cudaFuncSetAttribute(gemm_wmma_kernel,
                             cudaFuncAttributeMaxDynamicSharedMemorySize,
                             GEMM_SMEM_BYTES);
        attr_set = true;
    }

    // conversions + norm + CSR build
    x_to_h_kernel<<<(N_NODES * 32 + 255) / 256, 256>>>(x);
    w_to_h_kernel<<<(FDIM * FDIM + 255) / 256, 256>>>(W1, W2, W3);
    deg_init_kernel<<<(N_NODES + 255) / 256, 256>>>();
    deg_count_kernel<<<(N_EDGES + 255) / 256, 256>>>(col);
    dis_kernel<<<(N_NODES + 255) / 256, 256>>>();
    scanA_kernel<<<SCAN_NB, SCAN_B>>>();
    scanB_kernel<<<1, 32>>>();
    scanC_kernel<<<SCAN_NB, SCAN_B>>>();
    fill_kernel<<<(N_EDGES + 255) / 256, 256>>>(row, col);

    const int gemm_blocks = N_NODES / GEMM_BM;          // 625 exact
    const int node_warp_blocks = (N_NODES + 7) / 8;

    __half* X16; cudaGetSymbolAddress((void**)&X16, g_X16);
    __half* A16; cudaGetSymbolAddress((void**)&A16, g_A16);
    __half* B16; cudaGetSymbolAddress((void**)&B16, g_B16);
    __half* W16; cudaGetSymbolAddress((void**)&W16, g_W16);

    const __half* feat_in = X16;
    const float* biases[3] = {b1, b2, b3};

    for (int l = 0; l < 3; l++) {
        gemm_wmma_kernel<<<gemm_blocks, 256, GEMM_SMEM_BYTES>>>(
            feat_in, W16 + l * FDIM * FDIM, B16);
        gather_kernel<<<node_warp_blocks, 256>>>(biases[l]);
        feat_in = A16;
    }

    zero_pool_kernel<<<1, 256>>>();
    pool_kernel<<<node_warp_blocks, 256>>>(bat);
    final_kernel<<<N_GRAPHS, 32>>>(Wl, bl, out);
}

// round 5
// speedup vs baseline: 1.3304x; 1.3304x over previous
#include <cuda_runtime.h>
#include <cuda_fp16.h>
#include <mma.h>
#include <math.h>

using namespace nvcuda;

#define N_NODES   40000
#define N_EDGES   640000
#define FDIM      128
#define N_GRAPHS  64
#define N_CLASSES 10

#define SCAN_B    1024
#define SCAN_NB   ((N_NODES + SCAN_B - 1) / SCAN_B)   // 40

// ---------------- scratch (device globals; no allocations) ------------------
__device__ __align__(16) __half g_X16[N_NODES * FDIM];   // fp16 input features
__device__ __align__(16) __half g_A16[N_NODES * FDIM];   // layer outputs, fp16
__device__ __align__(16) __half g_B16[N_NODES * FDIM];   // gemm output, fp16
__device__ __align__(16) __half g_Whi[3 * FDIM * FDIM];  // W high halves
__device__ __align__(16) __half g_Wlo[3 * FDIM * FDIM];  // W residual halves
__device__ int    g_indeg[N_NODES];
__device__ float  g_dis[N_NODES];
__device__ int    g_off[N_NODES];
__device__ int    g_cursor[N_NODES];
__device__ int    g_bsum[SCAN_NB];
__device__ int2   g_srcwt[N_EDGES];        // CSR payload: (src row, norm bits)
__device__ float  g_sums[N_GRAPHS * FDIM];
__device__ float  g_cnts[N_GRAPHS];

// ---------------- conversions ------------------------------------------------
__global__ void x_to_h_kernel(const float* __restrict__ x) {
    int idx = blockIdx.x * blockDim.x + threadIdx.x;   // float4 units
    if (idx >= N_NODES * 32) return;
    float4 v = ((const float4*)x)[idx];
    __half2 h0 = __floats2half2_rn(v.x, v.y);
    __half2 h1 = __floats2half2_rn(v.z, v.w);
    uint2 u; u.x = *(unsigned*)&h0; u.y = *(unsigned*)&h1;
    ((uint2*)g_X16)[idx] = u;
}

// W = W_hi + W_lo (Markidis split): weight rounding error is correlated across
// pooled nodes, so it must be compensated; activation rounding averages out.
__global__ void w_split_kernel(const float* __restrict__ W1,
                               const float* __restrict__ W2,
                               const float* __restrict__ W3) {
    int idx = blockIdx.x * blockDim.x + threadIdx.x;
    if (idx >= FDIM * FDIM) return;
    const float* Ws[3] = {W1, W2, W3};
#pragma unroll
    for (int l = 0; l < 3; l++) {
        float w = Ws[l][idx];
        __half hi = __float2half_rn(w);
        float lo = w - __half2float(hi);
        g_Whi[l * FDIM * FDIM + idx] = hi;
        g_Wlo[l * FDIM * FDIM + idx] = __float2half_rn(lo);
    }
}

// ---------------- degree ----------------------------------------------------
__global__ void deg_init_kernel() {
    int i = blockIdx.x * blockDim.x + threadIdx.x;
    if (i < N_NODES) g_indeg[i] = 0;
}

__global__ void deg_count_kernel(const int* __restrict__ col) {
    int e = blockIdx.x * blockDim.x + threadIdx.x;
    if (e < N_EDGES) atomicAdd(&g_indeg[col[e]], 1);
}

__global__ void dis_kernel() {
    int i = blockIdx.x * blockDim.x + threadIdx.x;
    if (i < N_NODES) g_dis[i] = rsqrtf((float)(g_indeg[i] + 1));
}

// ---------------- exclusive scan of g_indeg -> g_off ------------------------
__global__ void scanA_kernel() {
    __shared__ int s[SCAN_B];
    int tid = threadIdx.x;
    int gid = blockIdx.x * SCAN_B + tid;
    int v = (gid < N_NODES) ? g_indeg[gid] : 0;
    s[tid] = v;
    __syncthreads();
#pragma unroll
    for (int off = 1; off < SCAN_B; off <<= 1) {
        int t = 0;
        if (tid >= off) t = s[tid - off];
        __syncthreads();
        if (tid >= off) s[tid] += t;
        __syncthreads();
    }
    if (gid < N_NODES) g_off[gid] = s[tid] - v;
    if (tid == SCAN_B - 1) g_bsum[blockIdx.x] = s[tid];
}

__global__ void scanB_kernel() {
    if (threadIdx.x == 0) {
        int run = 0;
        for (int i = 0; i < SCAN_NB; i++) {
            int t = g_bsum[i];
            g_bsum[i] = run;
            run += t;
        }
    }
}

__global__ void scanC_kernel() {
    int gid = blockIdx.x * SCAN_B + threadIdx.x;
    if (gid < N_NODES) {
        int o = g_off[gid] + g_bsum[blockIdx.x];
        g_off[gid] = o;
        g_cursor[gid] = o;
    }
}

// ---------------- CSR fill ---------------------------------------------------
__global__ void fill_kernel(const int* __restrict__ row,
                            const int* __restrict__ col) {
    int e = blockIdx.x * blockDim.x + threadIdx.x;
    if (e >= N_EDGES) return;
    int r = row[e];
    int c = col[e];
    int p = atomicAdd(&g_cursor[c], 1);
    float w = g_dis[r] * g_dis[c];
    g_srcwt[p] = make_int2(r, __float_as_int(w));
}

// ---------------- wmma GEMM: Y16 = X16 @ (Whi + Wlo) ------------------------
// Block 256 thr (8 warps). Tile 64 rows x 128 cols.
// smem rows padded to 136 halves (272B): consecutive rows shift by 16B ->
// conflict-free LDSM (vs 256B stride = all rows on one bank group in R4).
#define GEMM_BM  64
#define LDP      136                           // padded half stride
#define GEMM_SMEM_BYTES ((2 * 128 * LDP + GEMM_BM * LDP) * 2)   // ~87 KB
__global__ __launch_bounds__(256, 2)
void gemm_wmma_kernel(const __half* __restrict__ X,
                      const __half* __restrict__ Whi,
                      const __half* __restrict__ Wlo,
                      __half* __restrict__ Y) {
    extern __shared__ __half smh[];
    __half* Wh = smh;                    // 128 x LDP
    __half* Wl = smh + 128 * LDP;        // 128 x LDP
    __half* Xs = smh + 2 * 128 * LDP;    // 64  x LDP

    int tid  = threadIdx.x;
    int row0 = blockIdx.x * GEMM_BM;

    // stage W_hi, W_lo: 2048 float4 each (8 halves per float4)
    const float4* Wh4 = (const float4*)Whi;
    const float4* Wl4 = (const float4*)Wlo;
#pragma unroll
    for (int i = 0; i < 8; i++) {
        int idx = tid + 256 * i;
        int r = idx >> 4, c8 = idx & 15;
        *(float4*)(Wh + r * LDP + c8 * 8) = Wh4[idx];
        *(float4*)(Wl + r * LDP + c8 * 8) = Wl4[idx];
    }
    // stage X tile: 1024 float4
    const float4* X4 = (const float4*)(X + (size_t)row0 * FDIM);
#pragma unroll
    for (int i = 0; i < 4; i++) {
        int idx = tid + 256 * i;
        int r = idx >> 4, c8 = idx & 15;
        *(float4*)(Xs + r * LDP + c8 * 8) = X4[idx];
    }
    __syncthreads();

    int warp = tid >> 5;
    int wr = warp >> 1;        // 0..3 row tile (16 rows)
    int wc = warp & 1;         // 0..1 col half (64 cols)

    wmma::fragment<wmma::matrix_a, 16, 16, 16, __half, wmma::row_major> a_frag;
    wmma::fragment<wmma::matrix_b, 16, 16, 16, __half, wmma::row_major> bh, bl;
    wmma::fragment<wmma::accumulator, 16, 16, 16, float> acc[4];
#pragma unroll
    for (int j = 0; j < 4; j++) wmma::fill_fragment(acc[j], 0.0f);

#pragma unroll
    for (int kk = 0; kk < 8; kk++) {
        wmma::load_matrix_sync(a_frag, Xs + (wr * 16) * LDP + kk * 16, LDP);
#pragma unroll
        for (int j = 0; j < 4; j++) {
            int coff = wc * 64 + j * 16;
            wmma::load_matrix_sync(bh, Wh + (kk * 16) * LDP + coff, LDP);
            wmma::mma_sync(acc[j], a_frag, bh, acc[j]);
            wmma::load_matrix_sync(bl, Wl + (kk * 16) * LDP + coff, LDP);
            wmma::mma_sync(acc[j], a_frag, bl, acc[j]);
        }
    }

    // fp32 acc -> fp16 fragment (same logical element order), store direct
#pragma unroll
    for (int j = 0; j < 4; j++) {
        wmma::fragment<wmma::accumulator, 16, 16, 16, __half> hfrag;
#pragma unroll
        for (int t = 0; t < hfrag.num_elements; t++)
            hfrag.x[t] = __float2half_rn(acc[j].x[t]);
        wmma::store_matrix_sync(
            Y + (size_t)(row0 + wr * 16) * FDIM + wc * 64 + j * 16,
            hfrag, FDIM, wmma::mem_row_major);
    }
}

// ---------------- fp16 quad -> float4 ---------------------------------------
__device__ __forceinline__ float4 h4_to_f4(uint2 u) {
    __half2 a = *(__half2*)&u.x;
    __half2 b = *(__half2*)&u.y;
    float2 fa = __half22float2(a);
    float2 fb = __half22float2(b);
    return make_float4(fa.x, fa.y, fb.x, fb.y);
}

// ---------------- CSR gather: A16[n] = relu( sum_in + selfloop + bias ) -----
__global__ void gather_kernel(const float* __restrict__ bias) {
    int node = blockIdx.x * (blockDim.x >> 5) + (threadIdx.x >> 5);
    if (node >= N_NODES) return;
    int lane = threadIdx.x & 31;

    const uint2* B2 = (const uint2*)g_B16;

    int beg = g_off[node];
    int end = beg + g_indeg[node];

    float dn = g_dis[node];
    float sl = dn * dn;
    float4 sv = h4_to_f4(B2[(size_t)node * 32 + lane]);
    float4 acc = make_float4(sv.x * sl, sv.y * sl, sv.z * sl, sv.w * sl);

    int i = beg;
    for (; i + 2 <= end; i += 2) {
        int2 e0 = g_srcwt[i];
        int2 e1 = g_srcwt[i + 1];
        float w0 = __int_as_float(e0.y);
        float w1 = __int_as_float(e1.y);
        float4 v0 = h4_to_f4(B2[(size_t)e0.x * 32 + lane]);
        float4 v1 = h4_to_f4(B2[(size_t)e1.x * 32 + lane]);
        acc.x = fmaf(w0, v0.x, acc.x);  acc.y = fmaf(w0, v0.y, acc.y);
        acc.z = fmaf(w0, v0.z, acc.z);  acc.w = fmaf(w0, v0.w, acc.w);
        acc.x = fmaf(w1, v1.x, acc.x);  acc.y = fmaf(w1, v1.y, acc.y);
        acc.z = fmaf(w1, v1.z, acc.z);  acc.w = fmaf(w1, v1.w, acc.w);
    }
    if (i < end) {
        int2 e0 = g_srcwt[i];
        float w0 = __int_as_float(e0.y);
        float4 v0 = h4_to_f4(B2[(size_t)e0.x * 32 + lane]);
        acc.x = fmaf(w0, v0.x, acc.x);  acc.y = fmaf(w0, v0.y, acc.y);
        acc.z = fmaf(w0, v0.z, acc.z);  acc.w = fmaf(w0, v0.w, acc.w);
    }

    float4 bv = __ldg(&((const float4*)bias)[lane]);
    acc.x = fmaxf(acc.x + bv.x, 0.f);
    acc.y = fmaxf(acc.y + bv.y, 0.f);
    acc.z = fmaxf(acc.z + bv.z, 0.f);
    acc.w = fmaxf(acc.w + bv.w, 0.f);

    __half2 h0 = __floats2half2_rn(acc.x, acc.y);
    __half2 h1 = __floats2half2_rn(acc.z, acc.w);
    uint2 u; u.x = *(unsigned*)&h0; u.y = *(unsigned*)&h1;
    ((uint2*)g_A16)[(size_t)node * 32 + lane] = u;
}

// ---------------- pooling ----------------------------------------------------
__global__ void zero_pool_kernel() {
    int i = threadIdx.x;
    for (int k = i; k < N_GRAPHS * FDIM; k += blockDim.x) g_sums[k] = 0.f;
    if (i < N_GRAPHS) g_cnts[i] = 0.f;
}

__global__ void pool_kernel(const int* __restrict__ batch) {
    int node = blockIdx.x * (blockDim.x >> 5) + (threadIdx.x >> 5);
    if (node >= N_NODES) return;
    int lane = threadIdx.x & 31;
    int g = __ldg(&batch[node]);
    float4 v = h4_to_f4(((const uint2*)g_A16)[(size_t)node * 32 + lane]);
    float* dst = g_sums + (size_t)g * FDIM + lane * 4;
    asm volatile("red.global.add.v4.f32 [%0], {%1, %2, %3, %4};"
                 :: "l"(dst), "f"(v.x), "f"(v.y), "f"(v.z), "f"(v.w)
                 : "memory");
    if (lane == 0) atomicAdd(&g_cnts[g], 1.0f);
}

// ---------------- final linear ----------------------------------------------
__global__ void final_kernel(const float* __restrict__ Wl,
                             const float* __restrict__ bl,
                             float* __restrict__ out) {
    int g = blockIdx.x;
    int c = threadIdx.x;
    if (c >= N_CLASSES) return;
    float cnt = g_cnts[g];
    float inv = 1.0f / fmaxf(cnt, 1.0f);
    float acc = bl[c];
    for (int k = 0; k < FDIM; k++)
        acc += (g_sums[g * FDIM + k] * inv) * Wl[k * N_CLASSES + c];
    out[g * N_CLASSES + c] = acc;
}

// ---------------- launch ----------------------------------------------------
extern "C" void kernel_launch(void* const* d_in, const int* in_sizes, int n_in,
                              void* d_out, int out_size) {
    const float* x   = (const float*)d_in[0];
    const int*   ei  = (const int*)d_in[1];
    const int*   bat = (const int*)d_in[2];
    const float* W1  = (const float*)d_in[3];
    const float* b1  = (const float*)d_in[4];
    const float* W2  = (const float*)d_in[5];
    const float* b2  = (const float*)d_in[6];
    const float* W3  = (const float*)d_in[7];
    const float* b3  = (const float*)d_in[8];
    const float* Wl  = (const float*)d_in[9];
    const float* bl  = (const float*)d_in[10];
    float* out = (float*)d_out;

    const int* row = ei;
    const int* col = ei + N_EDGES;

    static bool attr_set = false;
    if (!attr_set) {
        cudaFuncSetAttribute(gemm_wmma_kernel,
                             cudaFuncAttributeMaxDynamicSharedMemorySize,
                             GEMM_SMEM_BYTES);
        attr_set = true;
    }

    // conversions + norm + CSR build
    x_to_h_kernel<<<(N_NODES * 32 + 255) / 256, 256>>>(x);
    w_split_kernel<<<(FDIM * FDIM + 255) / 256, 256>>>(W1, W2, W3);
    deg_init_kernel<<<(N_NODES + 255) / 256, 256>>>();
    deg_count_kernel<<<(N_EDGES + 255) / 256, 256>>>(col);
    dis_kernel<<<(N_NODES + 255) / 256, 256>>>();
    scanA_kernel<<<SCAN_NB, SCAN_B>>>();
    scanB_kernel<<<1, 32>>>();
    scanC_kernel<<<SCAN_NB, SCAN_B>>>();
    fill_kernel<<<(N_EDGES + 255) / 256, 256>>>(row, col);

    const int gemm_blocks = N_NODES / GEMM_BM;          // 625 exact
    const int node_warp_blocks = (N_NODES + 7) / 8;

    __half* X16; cudaGetSymbolAddress((void**)&X16, g_X16);
    __half* A16; cudaGetSymbolAddress((void**)&A16, g_A16);
    __half* B16; cudaGetSymbolAddress((void**)&B16, g_B16);
    __half* Whi; cudaGetSymbolAddress((void**)&Whi, g_Whi);
    __half* Wlo; cudaGetSymbolAddress((void**)&Wlo, g_Wlo);

    const __half* feat_in = X16;
    const float* biases[3] = {b1, b2, b3};

    for (int l = 0; l < 3; l++) {
        gemm_wmma_kernel<<<gemm_blocks, 256, GEMM_SMEM_BYTES>>>(
            feat_in, Whi + l * FDIM * FDIM, Wlo + l * FDIM * FDIM, B16);
        gather_kernel<<<node_warp_blocks, 256>>>(biases[l]);
        feat_in = A16;
    }

    zero_pool_kernel<<<1, 256>>>();
    pool_kernel<<<node_warp_blocks, 256>>>(bat);
    final_kernel<<<N_GRAPHS, 32>>>(Wl, bl, out);
}

// round 7
// speedup vs baseline: 1.4358x; 1.0792x over previous
#include <cuda_runtime.h>
#include <cuda_fp16.h>
#include <mma.h>
#include <math.h>

using namespace nvcuda;

#define N_NODES   40000
#define N_EDGES   640000
#define FDIM      128
#define N_GRAPHS  64
#define N_CLASSES 10

#define SCAN_B    1024
#define SCAN_NB   ((N_NODES + SCAN_B - 1) / SCAN_B)   // 40

// ---------------- scratch (device globals; no allocations) ------------------
__device__ __align__(16) __half g_X16[N_NODES * FDIM];
__device__ __align__(16) __half g_A16[N_NODES * FDIM];
__device__ __align__(16) __half g_B16[N_NODES * FDIM];
__device__ __align__(16) __half g_Whi[3 * FDIM * FDIM];
__device__ __align__(16) __half g_Wlo[3 * FDIM * FDIM];
__device__ int    g_indeg[N_NODES];
__device__ float  g_dis[N_NODES];
__device__ int    g_off[N_NODES];
__device__ int    g_cursor[N_NODES];
__device__ int    g_bsum[SCAN_NB];
__device__ int2   g_srcwt[N_EDGES];
__device__ float  g_sums[N_GRAPHS * FDIM];
__device__ float  g_cnts[N_GRAPHS];

// ---------------- conversions ------------------------------------------------
__global__ void x_to_h_kernel(const float* __restrict__ x) {
    int idx = blockIdx.x * blockDim.x + threadIdx.x;
    if (idx >= N_NODES * 32) return;
    float4 v = ((const float4*)x)[idx];
    __half2 h0 = __floats2half2_rn(v.x, v.y);
    __half2 h1 = __floats2half2_rn(v.z, v.w);
    uint2 u; u.x = *(unsigned*)&h0; u.y = *(unsigned*)&h1;
    ((uint2*)g_X16)[idx] = u;
}

__global__ void w_split_kernel(const float* __restrict__ W1,
                               const float* __restrict__ W2,
                               const float* __restrict__ W3) {
    int idx = blockIdx.x * blockDim.x + threadIdx.x;
    if (idx >= FDIM * FDIM) return;
    const float* Ws[3] = {W1, W2, W3};
#pragma unroll
    for (int l = 0; l < 3; l++) {
        float w = Ws[l][idx];
        __half hi = __float2half_rn(w);
        float lo = w - __half2float(hi);
        g_Whi[l * FDIM * FDIM + idx] = hi;
        g_Wlo[l * FDIM * FDIM + idx] = __float2half_rn(lo);
    }
}

// ---------------- degree ----------------------------------------------------
__global__ void deg_init_kernel() {
    int i = blockIdx.x * blockDim.x + threadIdx.x;
    if (i < N_NODES) g_indeg[i] = 0;
}

__global__ void deg_count_kernel(const int* __restrict__ col) {
    int e = blockIdx.x * blockDim.x + threadIdx.x;
    if (e < N_EDGES) atomicAdd(&g_indeg[col[e]], 1);
}

// ---------------- scan (dis fused into pass A) --------------------------------
__global__ void scanA_kernel() {
    __shared__ int s[SCAN_B];
    int tid = threadIdx.x;
    int gid = blockIdx.x * SCAN_B + tid;
    int v = (gid < N_NODES) ? g_indeg[gid] : 0;
    if (gid < N_NODES) g_dis[gid] = rsqrtf((float)(v + 1));
    s[tid] = v;
    __syncthreads();
#pragma unroll
    for (int off = 1; off < SCAN_B; off <<= 1) {
        int t = 0;
        if (tid >= off) t = s[tid - off];
        __syncthreads();
        if (tid >= off) s[tid] += t;
        __syncthreads();
    }
    if (gid < N_NODES) g_off[gid] = s[tid] - v;
    if (tid == SCAN_B - 1) g_bsum[blockIdx.x] = s[tid];
}

__global__ void scanB_kernel() {
    if (threadIdx.x == 0) {
        int run = 0;
        for (int i = 0; i < SCAN_NB; i++) {
            int t = g_bsum[i];
            g_bsum[i] = run;
            run += t;
        }
    }
}

__global__ void scanC_kernel() {
    int gid = blockIdx.x * SCAN_B + threadIdx.x;
    if (gid < N_NODES) {
        int o = g_off[gid] + g_bsum[blockIdx.x];
        g_off[gid] = o;
        g_cursor[gid] = o;
    }
}

// ---------------- CSR fill ---------------------------------------------------
__global__ void fill_kernel(const int* __restrict__ row,
                            const int* __restrict__ col) {
    int e = blockIdx.x * blockDim.x + threadIdx.x;
    if (e >= N_EDGES) return;
    int r = row[e];
    int c = col[e];
    int p = atomicAdd(&g_cursor[c], 1);
    float w = g_dis[r] * g_dis[c];
    g_srcwt[p] = make_int2(r, __float_as_int(w));
}

// ---------------- wmma GEMM: Y16 = X16 @ (Whi + Wlo) ------------------------
#define GEMM_BM  64
#define LDP      136
#define GEMM_SMEM_BYTES ((2 * 128 * LDP + GEMM_BM * LDP) * 2)
__global__ __launch_bounds__(256, 2)
void gemm_wmma_kernel(const __half* __restrict__ X,
                      const __half* __restrict__ Whi,
                      const __half* __restrict__ Wlo,
                      __half* __restrict__ Y) {
    extern __shared__ __half smh[];
    __half* Wh = smh;
    __half* Wl = smh + 128 * LDP;
    __half* Xs = smh + 2 * 128 * LDP;

    int tid  = threadIdx.x;
    int row0 = blockIdx.x * GEMM_BM;

    const float4* Wh4 = (const float4*)Whi;
    const float4* Wl4 = (const float4*)Wlo;
#pragma unroll
    for (int i = 0; i < 8; i++) {
        int idx = tid + 256 * i;
        int r = idx >> 4, c8 = idx & 15;
        *(float4*)(Wh + r * LDP + c8 * 8) = Wh4[idx];
        *(float4*)(Wl + r * LDP + c8 * 8) = Wl4[idx];
    }
    const float4* X4 = (const float4*)(X + (size_t)row0 * FDIM);
#pragma unroll
    for (int i = 0; i < 4; i++) {
        int idx = tid + 256 * i;
        int r = idx >> 4, c8 = idx & 15;
        *(float4*)(Xs + r * LDP + c8 * 8) = X4[idx];
    }
    __syncthreads();

    int warp = tid >> 5;
    int wr = warp >> 1;
    int wc = warp & 1;

    wmma::fragment<wmma::matrix_a, 16, 16, 16, __half, wmma::row_major> a_frag;
    wmma::fragment<wmma::matrix_b, 16, 16, 16, __half, wmma::row_major> bh, bl;
    wmma::fragment<wmma::accumulator, 16, 16, 16, float> acc[4];
#pragma unroll
    for (int j = 0; j < 4; j++) wmma::fill_fragment(acc[j], 0.0f);

#pragma unroll
    for (int kk = 0; kk < 8; kk++) {
        wmma::load_matrix_sync(a_frag, Xs + (wr * 16) * LDP + kk * 16, LDP);
#pragma unroll
        for (int j = 0; j < 4; j++) {
            int coff = wc * 64 + j * 16;
            wmma::load_matrix_sync(bh, Wh + (kk * 16) * LDP + coff, LDP);
            wmma::mma_sync(acc[j], a_frag, bh, acc[j]);
            wmma::load_matrix_sync(bl, Wl + (kk * 16) * LDP + coff, LDP);
            wmma::mma_sync(acc[j], a_frag, bl, acc[j]);
        }
    }

#pragma unroll
    for (int j = 0; j < 4; j++) {
        wmma::fragment<wmma::accumulator, 16, 16, 16, __half> hfrag;
#pragma unroll
        for (int t = 0; t < hfrag.num_elements; t++)
            hfrag.x[t] = __float2half_rn(acc[j].x[t]);
        wmma::store_matrix_sync(
            Y + (size_t)(row0 + wr * 16) * FDIM + wc * 64 + j * 16,
            hfrag, FDIM, wmma::mem_row_major);
    }
}

// ---------------- fp16 quad -> float4 ---------------------------------------
__device__ __forceinline__ float4 h4_to_f4(uint2 u) {
    __half2 a = *(__half2*)&u.x;
    __half2 b = *(__half2*)&u.y;
    float2 fa = __half22float2(a);
    float2 fb = __half22float2(b);
    return make_float4(fa.x, fa.y, fb.x, fb.y);
}

__device__ __forceinline__ void edge_fma(float4& acc, int src, float w,
                                         const uint2* B2, int lane) {
    float4 v = h4_to_f4(__ldg(&B2[(size_t)src * 32 + lane]));
    acc.x = fmaf(w, v.x, acc.x);
    acc.y = fmaf(w, v.y, acc.y);
    acc.z = fmaf(w, v.z, acc.z);
    acc.w = fmaf(w, v.w, acc.w);
}

// ---------------- CSR gather (lane-parallel CSR chunk + shfl broadcast) ------
// POOL=0: write relu(out) to g_A16 (fp16). POOL=1: red.add into g_sums.
template <int POOL>
__global__ void gather_kernel(const float* __restrict__ bias,
                              const int* __restrict__ batch) {
    int node = blockIdx.x * (blockDim.x >> 5) + (threadIdx.x >> 5);
    if (node >= N_NODES) return;
    int lane = threadIdx.x & 31;

    const uint2* B2 = (const uint2*)g_B16;

    int beg = g_off[node];
    int deg = g_indeg[node];

    float dn = g_dis[node];
    float sl = dn * dn;
    float4 sv = h4_to_f4(B2[(size_t)node * 32 + lane]);
    float4 acc = make_float4(sv.x * sl, sv.y * sl, sv.z * sl, sv.w * sl);

    for (int base = 0; base < deg; base += 32) {
        int rem = deg - base; if (rem > 32) rem = 32;
        int2 my = make_int2(0, 0);
        if (lane < rem) my = __ldg(&g_srcwt[beg + base + lane]);

        int j = 0;
        for (; j + 4 <= rem; j += 4) {
            int   s0 = __shfl_sync(0xffffffffu, my.x, j);
            int   s1 = __shfl_sync(0xffffffffu, my.x, j + 1);
            int   s2 = __shfl_sync(0xffffffffu, my.x, j + 2);
            int   s3 = __shfl_sync(0xffffffffu, my.x, j + 3);
            float w0 = __int_as_float(__shfl_sync(0xffffffffu, my.y, j));
            float w1 = __int_as_float(__shfl_sync(0xffffffffu, my.y, j + 1));
            float w2 = __int_as_float(__shfl_sync(0xffffffffu, my.y, j + 2));
            float w3 = __int_as_float(__shfl_sync(0xffffffffu, my.y, j + 3));
            float4 v0 = h4_to_f4(__ldg(&B2[(size_t)s0 * 32 + lane]));
            float4 v1 = h4_to_f4(__ldg(&B2[(size_t)s1 * 32 + lane]));
            float4 v2 = h4_to_f4(__ldg(&B2[(size_t)s2 * 32 + lane]));
            float4 v3 = h4_to_f4(__ldg(&B2[(size_t)s3 * 32 + lane]));
            acc.x = fmaf(w0, v0.x, acc.x); acc.y = fmaf(w0, v0.y, acc.y);
            acc.z = fmaf(w0, v0.z, acc.z); acc.w = fmaf(w0, v0.w, acc.w);
            acc.x = fmaf(w1, v1.x, acc.x); acc.y = fmaf(w1, v1.y, acc.y);
            acc.z = fmaf(w1, v1.z, acc.z); acc.w = fmaf(w1, v1.w, acc.w);
            acc.x = fmaf(w2, v2.x, acc.x); acc.y = fmaf(w2, v2.y, acc.y);
            acc.z = fmaf(w2, v2.z, acc.z); acc.w = fmaf(w2, v2.w, acc.w);
            acc.x = fmaf(w3, v3.x, acc.x); acc.y = fmaf(w3, v3.y, acc.y);
            acc.z = fmaf(w3, v3.z, acc.z); acc.w = fmaf(w3, v3.w, acc.w);
        }
        for (; j < rem; j++) {
            int   s = __shfl_sync(0xffffffffu, my.x, j);
            float w = __int_as_float(__shfl_sync(0xffffffffu, my.y, j));
            edge_fma(acc, s, w, B2, lane);
        }
    }

    float4 bv = __ldg(&((const float4*)bias)[lane]);
    acc.x = fmaxf(acc.x + bv.x, 0.f);
    acc.y = fmaxf(acc.y + bv.y, 0.f);
    acc.z = fmaxf(acc.z + bv.z, 0.f);
    acc.w = fmaxf(acc.w + bv.w, 0.f);

    if (POOL) {
        int g = __ldg(&batch[node]);
        float* dst = g_sums + (size_t)g * FDIM + lane * 4;
        asm volatile("red.global.add.v4.f32 [%0], {%1, %2, %3, %4};"
                     :: "l"(dst), "f"(acc.x), "f"(acc.y), "f"(acc.z), "f"(acc.w)
                     : "memory");
        if (lane == 0) atomicAdd(&g_cnts[g], 1.0f);
    } else {
        __half2 h0 = __floats2half2_rn(acc.x, acc.y);
        __half2 h1 = __floats2half2_rn(acc.z, acc.w);
        uint2 u; u.x = *(unsigned*)&h0; u.y = *(unsigned*)&h1;
        ((uint2*)g_A16)[(size_t)node * 32 + lane] = u;
    }
}

// ---------------- pooling ----------------------------------------------------
__global__ void zero_pool_kernel() {
    int i = threadIdx.x;
    for (int k = i; k < N_GRAPHS * FDIM; k += blockDim.x) g_sums[k] = 0.f;
    if (i < N_GRAPHS) g_cnts[i] = 0.f;
}

// ---------------- final linear ----------------------------------------------
__global__ void final_kernel(const float* __restrict__ Wl,
                             const float* __restrict__ bl,
                             float* __restrict__ out) {
    int g = blockIdx.x;
    int c = threadIdx.x;
    if (c >= N_CLASSES) return;
    float cnt = g_cnts[g];
    float inv = 1.0f / fmaxf(cnt, 1.0f);
    float acc = bl[c];
    for (int k = 0; k < FDIM; k++)
        acc += (g_sums[g * FDIM + k] * inv) * Wl[k * N_CLASSES + c];
    out[g * N_CLASSES + c] = acc;
}

// ---------------- launch ----------------------------------------------------
extern "C" void kernel_launch(void* const* d_in, const int* in_sizes, int n_in,
                              void* d_out, int out_size) {
    const float* x   = (const float*)d_in[0];
    const int*   ei  = (const int*)d_in[1];
    const int*   bat = (const int*)d_in[2];
    const float* W1  = (const float*)d_in[3];
    const float* b1  = (const float*)d_in[4];
    const float* W2  = (const float*)d_in[5];
    const float* b2  = (const float*)d_in[6];
    const float* W3  = (const float*)d_in[7];
    const float* b3  = (const float*)d_in[8];
    const float* Wl  = (const float*)d_in[9];
    const float* bl  = (const float*)d_in[10];
    float* out = (float*)d_out;

    const int* row = ei;
    const int* col = ei + N_EDGES;

    static cudaStream_t s1 = nullptr;
    static cudaEvent_t  ev_fork = nullptr, ev_join = nullptr;
    if (!s1) {
        cudaFuncSetAttribute(gemm_wmma_kernel,
                             cudaFuncAttributeMaxDynamicSharedMemorySize,
                             GEMM_SMEM_BYTES);
        cudaStreamCreateWithFlags(&s1, cudaStreamNonBlocking);
        cudaEventCreateWithFlags(&ev_fork, cudaEventDisableTiming);
        cudaEventCreateWithFlags(&ev_join, cudaEventDisableTiming);
    }

    const int gemm_blocks = N_NODES / GEMM_BM;          // 625
    const int node_warp_blocks = (N_NODES + 7) / 8;

    // device-symbol addresses (MUST go through cudaGetSymbolAddress on host)
    __half* X16; cudaGetSymbolAddress((void**)&X16, g_X16);
    __half* A16; cudaGetSymbolAddress((void**)&A16, g_A16);
    __half* B16; cudaGetSymbolAddress((void**)&B16, g_B16);
    __half* Whi; cudaGetSymbolAddress((void**)&Whi, g_Whi);
    __half* Wlo; cudaGetSymbolAddress((void**)&Wlo, g_Wlo);

    // fork: CSR build on side stream, overlapped with conversions + gemm1
    cudaEventRecord(ev_fork, 0);
    cudaStreamWaitEvent(s1, ev_fork, 0);

    deg_init_kernel<<<(N_NODES + 255) / 256, 256, 0, s1>>>();
    deg_count_kernel<<<(N_EDGES + 255) / 256, 256, 0, s1>>>(col);
    scanA_kernel<<<SCAN_NB, SCAN_B, 0, s1>>>();
    scanB_kernel<<<1, 32, 0, s1>>>();
    scanC_kernel<<<SCAN_NB, SCAN_B, 0, s1>>>();
    fill_kernel<<<(N_EDGES + 255) / 256, 256, 0, s1>>>(row, col);
    zero_pool_kernel<<<1, 256, 0, s1>>>();
    cudaEventRecord(ev_join, s1);

    // main stream
    x_to_h_kernel<<<(N_NODES * 32 + 255) / 256, 256>>>(x);
    w_split_kernel<<<(FDIM * FDIM + 255) / 256, 256>>>(W1, W2, W3);
    gemm_wmma_kernel<<<gemm_blocks, 256, GEMM_SMEM_BYTES>>>(X16, Whi, Wlo, B16);
    // join before first gather (needs CSR)
    cudaStreamWaitEvent(0, ev_join, 0);

    gather_kernel<0><<<node_warp_blocks, 256>>>(b1, bat);
    gemm_wmma_kernel<<<gemm_blocks, 256, GEMM_SMEM_BYTES>>>(
        A16, Whi + FDIM * FDIM, Wlo + FDIM * FDIM, B16);
    gather_kernel<0><<<node_warp_blocks, 256>>>(b2, bat);
    gemm_wmma_kernel<<<gemm_blocks, 256, GEMM_SMEM_BYTES>>>(
        A16, Whi + 2 * FDIM * FDIM, Wlo + 2 * FDIM * FDIM, B16);
    gather_kernel<1><<<node_warp_blocks, 256>>>(b3, bat);

    final_kernel<<<N_GRAPHS, 32>>>(Wl, bl, out);
}